// round 7
// baseline (speedup 1.0000x reference)
#include <cuda_runtime.h>
#include <math.h>

#define MAXN 100000
#define MAXE 3200000
#define NG 256

// ---------------- device scratch (no allocations allowed) ----------------
__device__ int    g_is32_ei;            // 1 if edge_index is int32, 0 if int64
__device__ int    g_is32_b;             // 1 if batch is int32, 0 if int64
__device__ int    g_src[MAXE];          // normalized int32 src (clamped)
__device__ int    g_dst[MAXE];          // normalized int32 dst (clamped)
__device__ int    g_batch[MAXN];        // normalized int32 batch (clamped)
__device__ int    g_degI[MAXN];         // degree counters (incl. self loop)
__device__ float  g_dinv[MAXN];         // rsqrt(deg)
__device__ float4 g_g1[MAXN * 4];       // pre-scaled features (layer1, reused by layer2) [N,16]
__device__ float4 g_out1[MAXN * 4];     // layer1 scatter accumulator [N,16]
__device__ float4 g_out2[MAXN * 4];     // layer2 scatter accumulator [N,16]
__device__ float4 g_pool[NG * 4];       // per-graph sums [256,16]
__device__ int    g_cnt[NG];            // per-graph node counts

// vector global reduction: 1 instruction, 16 bytes
__device__ __forceinline__ void red_add_v4(float4* addr, float4 v) {
    asm volatile("red.global.add.v4.f32 [%0], {%1,%2,%3,%4};"
                 :: "l"(addr), "f"(v.x), "f"(v.y), "f"(v.z), "f"(v.w)
                 : "memory");
}

__device__ __forceinline__ float4 f4_fma(float s, float4 w, float4 a) {
    a.x = fmaf(s, w.x, a.x);
    a.y = fmaf(s, w.y, a.y);
    a.z = fmaf(s, w.z, a.z);
    a.w = fmaf(s, w.w, a.w);
    return a;
}
__device__ __forceinline__ float4 f4_scale(float4 a, float s) {
    return make_float4(a.x * s, a.y * s, a.z * s, a.w * s);
}
__device__ __forceinline__ float4 f4_add(float4 a, float4 b) {
    return make_float4(a.x + b.x, a.y + b.y, a.z + b.z, a.w + b.w);
}
__device__ __forceinline__ float4 f4_relu(float4 a) {
    return make_float4(fmaxf(a.x, 0.f), fmaxf(a.y, 0.f), fmaxf(a.z, 0.f), fmaxf(a.w, 0.f));
}

// ---------------- kernels ----------------
// NOTE: no __device__ symbol is ever passed as a kernel argument from host
// code; all scratch is referenced directly inside device code.

// reset all accumulators + dtype flags (graph replays must be idempotent)
__global__ void __launch_bounds__(256) k_init(int N) {
    int i = blockIdx.x * blockDim.x + threadIdx.x;
    if (i < N)      g_degI[i] = 1;              // self-loop
    if (i < NG * 4) g_pool[i] = make_float4(0.f, 0.f, 0.f, 0.f);
    if (i < NG)     g_cnt[i]  = 0;
    if (i == 0) { g_is32_ei = 0; g_is32_b = 0; }
}

// dtype probe: sample odd dwords buf[off + 2*k*stride + 1] for k < nsamp.
// int64 data (values < 2^31) has all-zero odd dwords; int32 index data does not.
// WHICH selects the destination flag (0 = edge_index, 1 = batch).
template <int WHICH>
__global__ void __launch_bounds__(256) k_detect(const unsigned* __restrict__ buf,
                                                long long off, int nsamp, long long stride) {
    int k = blockIdx.x * blockDim.x + threadIdx.x;
    int v = 0;
    if (k < nsamp) v = (buf[off + 2LL * k * stride + 1] != 0u) ? 1 : 0;
    int any = __syncthreads_or(v);
    if (threadIdx.x == 0 && any) {
        if (WHICH == 0) atomicOr(&g_is32_ei, 1);
        else            atomicOr(&g_is32_b, 1);
    }
}

// normalize edge_index to int32 (clamped to [0,N)) and count degrees
__global__ void __launch_bounds__(256) k_norm_ei(const void* __restrict__ ei, int E, int N) {
    int e = blockIdx.x * blockDim.x + threadIdx.x;
    if (e >= E) return;
    int s, d;
    if (g_is32_ei) {
        const int* p = (const int*)ei;
        s = p[e]; d = p[E + e];
    } else {
        const long long* p = (const long long*)ei;
        s = (int)p[e]; d = (int)p[E + e];
    }
    s = min(max(s, 0), N - 1);
    d = min(max(d, 0), N - 1);
    g_src[e] = s;
    g_dst[e] = d;
    atomicAdd(&g_degI[d], 1);
}

__global__ void __launch_bounds__(256) k_norm_b(const void* __restrict__ b, int N) {
    int n = blockIdx.x * blockDim.x + threadIdx.x;
    if (n >= N) return;
    int v = g_is32_b ? ((const int*)b)[n] : (int)((const long long*)b)[n];
    g_batch[n] = min(max(v, 0), NG - 1);
}

__global__ void __launch_bounds__(256) k_dinv(int N) {
    int n = blockIdx.x * blockDim.x + threadIdx.x;
    if (n < N) g_dinv[n] = rsqrtf((float)g_degI[n]);
}

// h1 = x @ W1 ; g1 = h1 * dinv ; out1 = g1 * dinv (self-loop contribution)
__global__ void __launch_bounds__(256) k_gemm1(const float* __restrict__ x,
                                               const float* __restrict__ W1, int N) {
    __shared__ float4 Ws[512];   // W1 as [128 rows][4 float4-cols]
    int t = threadIdx.x;
    Ws[t]       = ((const float4*)W1)[t];
    Ws[t + 256] = ((const float4*)W1)[t + 256];
    __syncthreads();

    int n = blockIdx.x * 256 + t;
    if (n >= N) return;

    float4 a0 = make_float4(0.f, 0.f, 0.f, 0.f);
    float4 a1 = a0, a2 = a0, a3 = a0;
    const float4* xr = (const float4*)(x + (size_t)n * 128);

#pragma unroll 4
    for (int k4 = 0; k4 < 32; k4++) {
        float4 xv = __ldg(&xr[k4]);
        const float4* w = &Ws[(k4 * 4) * 4];
        a0 = f4_fma(xv.x, w[0],  a0); a1 = f4_fma(xv.x, w[1],  a1);
        a2 = f4_fma(xv.x, w[2],  a2); a3 = f4_fma(xv.x, w[3],  a3);
        a0 = f4_fma(xv.y, w[4],  a0); a1 = f4_fma(xv.y, w[5],  a1);
        a2 = f4_fma(xv.y, w[6],  a2); a3 = f4_fma(xv.y, w[7],  a3);
        a0 = f4_fma(xv.z, w[8],  a0); a1 = f4_fma(xv.z, w[9],  a1);
        a2 = f4_fma(xv.z, w[10], a2); a3 = f4_fma(xv.z, w[11], a3);
        a0 = f4_fma(xv.w, w[12], a0); a1 = f4_fma(xv.w, w[13], a1);
        a2 = f4_fma(xv.w, w[14], a2); a3 = f4_fma(xv.w, w[15], a3);
    }

    float di = g_dinv[n];
    a0 = f4_scale(a0, di); a1 = f4_scale(a1, di);
    a2 = f4_scale(a2, di); a3 = f4_scale(a3, di);
    g_g1[n * 4 + 0] = a0; g_g1[n * 4 + 1] = a1;
    g_g1[n * 4 + 2] = a2; g_g1[n * 4 + 3] = a3;
    g_out1[n * 4 + 0] = f4_scale(a0, di); g_out1[n * 4 + 1] = f4_scale(a1, di);
    g_out1[n * 4 + 2] = f4_scale(a2, di); g_out1[n * 4 + 3] = f4_scale(a3, di);
}

// edge scatter: out[dst] += g[src] * dinv[dst]   (4 threads per edge, float4 each)
// LAYER selects buffers in DEVICE code (symbols resolve to device addresses here).
template <int LAYER>
__global__ void __launch_bounds__(256) k_scatter(int E) {
    const float4* __restrict__ g = g_g1;
    float4* __restrict__ out = (LAYER == 1) ? g_out1 : g_out2;
    int t = blockIdx.x * blockDim.x + threadIdx.x;
    int e = t >> 2;
    int q = t & 3;
    if (e >= E) return;
    int s = __ldg(&g_src[e]);
    int d = __ldg(&g_dst[e]);
    float w = __ldg(&g_dinv[d]);
    float4 v = __ldg(&g[(size_t)s * 4 + q]);
    red_add_v4(&out[(size_t)d * 4 + q], f4_scale(v, w));
}

// t = relu(out1 + b1) ; h2 = t @ W2 ; g2 = h2*dinv (stored into g_g1) ; out2 = g2*dinv
__global__ void __launch_bounds__(256) k_post1(const float* __restrict__ b1,
                                               const float* __restrict__ W2, int N) {
    __shared__ float4 W2s[64];   // [16 rows][4 float4-cols]
    __shared__ float4 b1s[4];
    int t = threadIdx.x;
    if (t < 64) W2s[t] = ((const float4*)W2)[t];
    if (t < 4)  b1s[t] = ((const float4*)b1)[t];
    __syncthreads();

    int n = blockIdx.x * 256 + t;
    if (n >= N) return;

    float tv[16];
#pragma unroll
    for (int i = 0; i < 4; i++) {
        float4 o = f4_relu(f4_add(g_out1[n * 4 + i], b1s[i]));
        tv[i * 4 + 0] = o.x; tv[i * 4 + 1] = o.y;
        tv[i * 4 + 2] = o.z; tv[i * 4 + 3] = o.w;
    }

    float4 a0 = make_float4(0.f, 0.f, 0.f, 0.f);
    float4 a1 = a0, a2 = a0, a3 = a0;
#pragma unroll
    for (int j = 0; j < 16; j++) {
        float s = tv[j];
        a0 = f4_fma(s, W2s[j * 4 + 0], a0);
        a1 = f4_fma(s, W2s[j * 4 + 1], a1);
        a2 = f4_fma(s, W2s[j * 4 + 2], a2);
        a3 = f4_fma(s, W2s[j * 4 + 3], a3);
    }

    float di = g_dinv[n];
    a0 = f4_scale(a0, di); a1 = f4_scale(a1, di);
    a2 = f4_scale(a2, di); a3 = f4_scale(a3, di);
    // layer-1 g values are dead after scatter-1; reuse the buffer for layer-2
    g_g1[n * 4 + 0] = a0; g_g1[n * 4 + 1] = a1;
    g_g1[n * 4 + 2] = a2; g_g1[n * 4 + 3] = a3;
    g_out2[n * 4 + 0] = f4_scale(a0, di); g_out2[n * 4 + 1] = f4_scale(a1, di);
    g_out2[n * 4 + 2] = f4_scale(a2, di); g_out2[n * 4 + 3] = f4_scale(a3, di);
}

// pooled sums: pool[batch[n]] += out2[n] + b2 ; counts
__global__ void __launch_bounds__(256) k_pool(const float* __restrict__ b2, int N) {
    int t = blockIdx.x * blockDim.x + threadIdx.x;
    int n = t >> 2;
    int q = t & 3;
    if (n >= N) return;
    int b = __ldg(&g_batch[n]);
    float4 y = f4_add(g_out2[(size_t)n * 4 + q], __ldg(&((const float4*)b2)[q]));
    red_add_v4(&g_pool[b * 4 + q], y);
    if (q == 0) atomicAdd(&g_cnt[b], 1);
}

__global__ void __launch_bounds__(256) k_final(float* __restrict__ out) {
    int i = blockIdx.x * blockDim.x + threadIdx.x;
    if (i >= NG * 16) return;
    int g = i >> 4;
    float c = fmaxf((float)g_cnt[g], 1.0f);
    float s = ((const float*)g_pool)[i] / c;
    out[i] = 1.0f / (1.0f + expf(-s));
}

// ---------------- launch ----------------
// Plain stub-style launches on the default stream. No static constructors, no
// runtime API calls besides kernel launches (graph-capture safe).
extern "C" void kernel_launch(void* const* d_in, const int* in_sizes, int n_in,
                              void* d_out, int out_size) {
    const float* x     = (const float*)d_in[0];
    const void*  ei    = d_in[1];               // [2, E] int32 OR int64 (probed)
    const void*  batch = d_in[2];               // [N]    int32 OR int64 (probed)
    const float* W1    = (const float*)d_in[3];
    const float* b1    = (const float*)d_in[4];
    const float* W2    = (const float*)d_in[5];
    const float* b2    = (const float*)d_in[6];
    float* out = (float*)d_out;

    int N = in_sizes[0] / 128;
    int E = in_sizes[1] / 2;

    int nb_nodes = (N + 255) / 256;
    int nb_edges = (E + 255) / 256;
    int nb_edge4 = (4 * E + 255) / 256;
    int nb_node4 = (4 * N + 255) / 256;

    k_init<<<nb_nodes, 256>>>(N);

    // probe edge_index: sample odd dwords (stride 64) across its first 2E dwords
    {
        int nsamp = E / 64;
        if (nsamp > 0)
            k_detect<0><<<(nsamp + 255) / 256, 256>>>((const unsigned*)ei, 0, nsamp, 64);
    }
    // probe batch: sample odd dwords in the sorted tail (values ~ NG-1, nonzero if int32)
    {
        long long off = (N > 4096) ? (long long)((N - 4096) & ~1) : 0;
        int nsamp = (int)((N - off) / 2);
        if (nsamp > 0)
            k_detect<1><<<(nsamp + 255) / 256, 256>>>((const unsigned*)batch, off, nsamp, 1);
    }

    k_norm_ei<<<nb_edges, 256>>>(ei, E, N);     // also accumulates degrees
    k_norm_b<<<nb_nodes, 256>>>(batch, N);
    k_dinv<<<nb_nodes, 256>>>(N);
    k_gemm1<<<nb_nodes, 256>>>(x, W1, N);
    k_scatter<1><<<nb_edge4, 256>>>(E);
    k_post1<<<nb_nodes, 256>>>(b1, W2, N);
    k_scatter<2><<<nb_edge4, 256>>>(E);
    k_pool<<<nb_node4, 256>>>(b2, N);
    k_final<<<(NG * 16 + 255) / 256, 256>>>(out);
}

// round 8
// speedup vs baseline: 1.3045x; 1.3045x over previous
#include <cuda_runtime.h>
#include <math.h>

#define MAXN 100000
#define MAXE 3200000
#define NG 256

// ---------------- device scratch (no allocations allowed) ----------------
__device__ int    g_is32_ei;            // 1 if edge_index is int32, 0 if int64
__device__ int    g_is32_b;             // 1 if batch is int32, 0 if int64
__device__ int    g_deg[MAXN];          // edge-only in-degree
__device__ int    g_rowp[MAXN];         // CSR row start (exclusive prefix of deg)
__device__ int    g_cursor[MAXN];       // placement cursors
__device__ int    g_bsum[512];          // block sums for 2-level scan
__device__ int    g_perm[MAXE];         // src node id, grouped by dst
__device__ float  g_dinv[MAXN];         // rsqrt(deg+1)
__device__ float4 g_g1[MAXN * 4];       // layer1 pre-scaled features g1 = h1*dinv  [N,16]
__device__ float4 g_g2[MAXN * 4];       // layer2 pre-scaled features g2 = h2*dinv  [N,16]
__device__ float4 g_pool[NG * 4];       // per-graph sums [256,16]
__device__ int    g_cnt[NG];            // per-graph node counts

__device__ __forceinline__ void red_add_v4(float4* addr, float4 v) {
    asm volatile("red.global.add.v4.f32 [%0], {%1,%2,%3,%4};"
                 :: "l"(addr), "f"(v.x), "f"(v.y), "f"(v.z), "f"(v.w)
                 : "memory");
}
__device__ __forceinline__ float4 f4_fma(float s, float4 w, float4 a) {
    a.x = fmaf(s, w.x, a.x); a.y = fmaf(s, w.y, a.y);
    a.z = fmaf(s, w.z, a.z); a.w = fmaf(s, w.w, a.w);
    return a;
}
__device__ __forceinline__ float4 f4_scale(float4 a, float s) {
    return make_float4(a.x * s, a.y * s, a.z * s, a.w * s);
}
__device__ __forceinline__ float4 f4_add(float4 a, float4 b) {
    return make_float4(a.x + b.x, a.y + b.y, a.z + b.z, a.w + b.w);
}
// dtype-aware index load (int32 or int64 buffer), clamped to [0, hi)
__device__ __forceinline__ int load_idx(const void* p, long long i, int is32, int hi) {
    int v = is32 ? ((const int*)p)[i] : (int)((const long long*)p)[i];
    return min(max(v, 0), hi - 1);
}

// ---------------- kernels ----------------

__global__ void __launch_bounds__(256) k_init(int N) {
    int i = blockIdx.x * blockDim.x + threadIdx.x;
    if (i < N)      g_deg[i] = 0;
    if (i < NG * 4) g_pool[i] = make_float4(0.f, 0.f, 0.f, 0.f);
    if (i < NG)     g_cnt[i]  = 0;
    if (i == 0) { g_is32_ei = 0; g_is32_b = 0; }
}

// dtype probe: odd dwords of int64 index data (< 2^31) are all zero.
template <int WHICH>
__global__ void __launch_bounds__(256) k_detect(const unsigned* __restrict__ buf,
                                                long long off, int nsamp, long long stride) {
    int k = blockIdx.x * blockDim.x + threadIdx.x;
    int v = 0;
    if (k < nsamp) v = (buf[off + 2LL * k * stride + 1] != 0u) ? 1 : 0;
    int any = __syncthreads_or(v);
    if (threadIdx.x == 0 && any) {
        if (WHICH == 0) atomicOr(&g_is32_ei, 1);
        else            atomicOr(&g_is32_b, 1);
    }
}

__global__ void __launch_bounds__(256) k_deg(const void* __restrict__ ei, int E, int N) {
    int e = blockIdx.x * blockDim.x + threadIdx.x;
    if (e >= E) return;
    int d = load_idx(ei, (long long)E + e, g_is32_ei, N);
    atomicAdd(&g_deg[d], 1);
}

// 2-level exclusive scan of g_deg -> g_rowp
__global__ void __launch_bounds__(256) k_scan1(int N) {
    __shared__ int sh[256];
    int t = threadIdx.x;
    int i = blockIdx.x * 256 + t;
    int v = (i < N) ? g_deg[i] : 0;
    sh[t] = v;
    __syncthreads();
    for (int off = 1; off < 256; off <<= 1) {
        int add = (t >= off) ? sh[t - off] : 0;
        __syncthreads();
        sh[t] += add;
        __syncthreads();
    }
    if (i < N) g_rowp[i] = sh[t] - v;            // exclusive within block
    if (t == 255) g_bsum[blockIdx.x] = sh[255];  // block total
}

__global__ void __launch_bounds__(512) k_scan2(int nb) {
    __shared__ int sh[512];
    int t = threadIdx.x;
    int v = (t < nb) ? g_bsum[t] : 0;
    sh[t] = v;
    __syncthreads();
    for (int off = 1; off < 512; off <<= 1) {
        int add = (t >= off) ? sh[t - off] : 0;
        __syncthreads();
        sh[t] += add;
        __syncthreads();
    }
    if (t < nb) g_bsum[t] = sh[t] - v;           // exclusive block offsets
}

__global__ void __launch_bounds__(256) k_scan3(int N) {
    int i = blockIdx.x * blockDim.x + threadIdx.x;
    if (i >= N) return;
    int r = g_rowp[i] + g_bsum[i >> 8];
    g_rowp[i]   = r;
    g_cursor[i] = r;
    g_dinv[i]   = rsqrtf((float)(g_deg[i] + 1));  // +1 self loop
}

// place src ids grouped by dst
__global__ void __launch_bounds__(256) k_place(const void* __restrict__ ei, int E, int N) {
    int e = blockIdx.x * blockDim.x + threadIdx.x;
    if (e >= E) return;
    int is32 = g_is32_ei;
    int s = load_idx(ei, e, is32, N);
    int d = load_idx(ei, (long long)E + e, is32, N);
    int slot = atomicAdd(&g_cursor[d], 1);
    g_perm[slot] = s;
}

// g1 = (x @ W1) * dinv
__global__ void __launch_bounds__(256) k_gemm1(const float* __restrict__ x,
                                               const float* __restrict__ W1, int N) {
    __shared__ float4 Ws[512];   // W1 as [128 rows][4 float4-cols]
    int t = threadIdx.x;
    Ws[t]       = ((const float4*)W1)[t];
    Ws[t + 256] = ((const float4*)W1)[t + 256];
    __syncthreads();

    int n = blockIdx.x * 256 + t;
    if (n >= N) return;

    float4 a0 = make_float4(0.f, 0.f, 0.f, 0.f);
    float4 a1 = a0, a2 = a0, a3 = a0;
    const float4* xr = (const float4*)(x + (size_t)n * 128);

#pragma unroll 4
    for (int k4 = 0; k4 < 32; k4++) {
        float4 xv = __ldg(&xr[k4]);
        const float4* w = &Ws[(k4 * 4) * 4];
        a0 = f4_fma(xv.x, w[0],  a0); a1 = f4_fma(xv.x, w[1],  a1);
        a2 = f4_fma(xv.x, w[2],  a2); a3 = f4_fma(xv.x, w[3],  a3);
        a0 = f4_fma(xv.y, w[4],  a0); a1 = f4_fma(xv.y, w[5],  a1);
        a2 = f4_fma(xv.y, w[6],  a2); a3 = f4_fma(xv.y, w[7],  a3);
        a0 = f4_fma(xv.z, w[8],  a0); a1 = f4_fma(xv.z, w[9],  a1);
        a2 = f4_fma(xv.z, w[10], a2); a3 = f4_fma(xv.z, w[11], a3);
        a0 = f4_fma(xv.w, w[12], a0); a1 = f4_fma(xv.w, w[13], a1);
        a2 = f4_fma(xv.w, w[14], a2); a3 = f4_fma(xv.w, w[15], a3);
    }

    float di = g_dinv[n];
    g_g1[n * 4 + 0] = f4_scale(a0, di); g_g1[n * 4 + 1] = f4_scale(a1, di);
    g_g1[n * 4 + 2] = f4_scale(a2, di); g_g1[n * 4 + 3] = f4_scale(a3, di);
}

// segmented sum of g over node's incoming edges, seeded with self-loop g[n]
__device__ __forceinline__ float4 seg_sum(const float4* __restrict__ g, int n, int q) {
    int start = g_rowp[n];
    int end   = start + g_deg[n];
    float4 acc = g[(size_t)n * 4 + q];          // self loop
    int e = start;
    for (; e + 2 <= end; e += 2) {
        int s0 = __ldg(&g_perm[e]);
        int s1 = __ldg(&g_perm[e + 1]);
        float4 v0 = __ldg(&g[(size_t)s0 * 4 + q]);
        float4 v1 = __ldg(&g[(size_t)s1 * 4 + q]);
        acc = f4_add(acc, f4_add(v0, v1));
    }
    if (e < end) {
        int s0 = __ldg(&g_perm[e]);
        acc = f4_add(acc, __ldg(&g[(size_t)s0 * 4 + q]));
    }
    return acc;
}

// reduce layer1 + fused: t = relu(dinv*acc + b1); h2 = t @ W2; g2 = h2*dinv
// NOTE: no early return (shuffles need full warps); stores predicated.
__global__ void __launch_bounds__(256) k_reduce1(const float* __restrict__ b1,
                                                 const float* __restrict__ W2, int N) {
    __shared__ float4 W2s[64];
    __shared__ float4 b1s[4];
    int t = threadIdx.x;
    if (t < 64) W2s[t] = ((const float4*)W2)[t];
    if (t < 4)  b1s[t] = ((const float4*)b1)[t];
    __syncthreads();

    int gid = blockIdx.x * 256 + t;
    int n = gid >> 2;
    int q = gid & 3;
    bool valid = (n < N);
    int nc = valid ? n : (N - 1);

    float4 acc = seg_sum(g_g1, nc, q);
    float di = g_dinv[nc];
    float4 o = f4_fma(di, acc, b1s[q]);          // dinv*acc + b1
    float tv0 = fmaxf(o.x, 0.f), tv1 = fmaxf(o.y, 0.f);
    float tv2 = fmaxf(o.z, 0.f), tv3 = fmaxf(o.w, 0.f);

    // 16x16 GEMM across the quad via shuffles
    float4 a = make_float4(0.f, 0.f, 0.f, 0.f);
    int lane = threadIdx.x & 31;
    int base = lane & ~3;
#pragma unroll
    for (int j = 0; j < 16; j++) {
        float tj;
        float src = (j & 3) == 0 ? tv0 : (j & 3) == 1 ? tv1 : (j & 3) == 2 ? tv2 : tv3;
        tj = __shfl_sync(0xFFFFFFFFu, src, base + (j >> 2));
        a = f4_fma(tj, W2s[j * 4 + q], a);
    }
    if (valid) g_g2[(size_t)n * 4 + q] = f4_scale(a, di);
}

// reduce layer2 + fused mean-pool accumulate
__global__ void __launch_bounds__(256) k_reduce2(const void* __restrict__ batch,
                                                 const float* __restrict__ b2, int N) {
    int gid = blockIdx.x * blockDim.x + threadIdx.x;
    int n = gid >> 2;
    int q = gid & 3;
    if (n >= N) return;

    float4 acc = seg_sum(g_g2, n, q);
    float di = g_dinv[n];
    float4 y = f4_fma(di, acc, __ldg(&((const float4*)b2)[q]));  // dinv*acc + b2

    int b = load_idx(batch, n, g_is32_b, NG);
    red_add_v4(&g_pool[b * 4 + q], y);
    if (q == 0) atomicAdd(&g_cnt[b], 1);
}

__global__ void __launch_bounds__(256) k_final(float* __restrict__ out) {
    int i = blockIdx.x * blockDim.x + threadIdx.x;
    if (i >= NG * 16) return;
    int g = i >> 4;
    float c = fmaxf((float)g_cnt[g], 1.0f);
    float s = ((const float*)g_pool)[i] / c;
    out[i] = 1.0f / (1.0f + expf(-s));
}

// ---------------- launch ----------------
extern "C" void kernel_launch(void* const* d_in, const int* in_sizes, int n_in,
                              void* d_out, int out_size) {
    const float* x     = (const float*)d_in[0];
    const void*  ei    = d_in[1];               // [2, E] int32 OR int64 (probed)
    const void*  batch = d_in[2];               // [N]    int32 OR int64 (probed)
    const float* W1    = (const float*)d_in[3];
    const float* b1    = (const float*)d_in[4];
    const float* W2    = (const float*)d_in[5];
    const float* b2    = (const float*)d_in[6];
    float* out = (float*)d_out;

    int N = in_sizes[0] / 128;
    int E = in_sizes[1] / 2;

    int nb_nodes = (N + 255) / 256;
    int nb_edges = (E + 255) / 256;
    int nb_node4 = (4 * N + 255) / 256;

    k_init<<<nb_nodes, 256>>>(N);

    // dtype probes
    {
        int nsamp = E / 64;
        if (nsamp > 0)
            k_detect<0><<<(nsamp + 255) / 256, 256>>>((const unsigned*)ei, 0, nsamp, 64);
    }
    {
        long long off = (N > 4096) ? (long long)((N - 4096) & ~1) : 0;
        int nsamp = (int)((N - off) / 2);
        if (nsamp > 0)
            k_detect<1><<<(nsamp + 255) / 256, 256>>>((const unsigned*)batch, off, nsamp, 1);
    }

    // CSR build
    k_deg<<<nb_edges, 256>>>(ei, E, N);
    k_scan1<<<nb_nodes, 256>>>(N);
    k_scan2<<<1, 512>>>(nb_nodes);
    k_scan3<<<nb_nodes, 256>>>(N);
    k_place<<<nb_edges, 256>>>(ei, E, N);

    // pipeline
    k_gemm1<<<nb_nodes, 256>>>(x, W1, N);
    k_reduce1<<<nb_node4, 256>>>(b1, W2, N);
    k_reduce2<<<nb_node4, 256>>>(batch, b2, N);
    k_final<<<(NG * 16 + 255) / 256, 256>>>(out);
}